// round 15
// baseline (speedup 1.0000x reference)
#include <cuda_runtime.h>
#include <cuda_fp16.h>
#include <cstdint>
#include <math.h>

// ---------------------------------------------------------------------------
// MinGPT forward.  B=4, S=1024, D=1024, H=16, HS=64, L=4, DFF=4096, V=32000.
// Round 15: chunk-wise fp16-accumulate HMMA in the GEMM (promote to fp32
// every K=64), testing the f16-accum 2x-rate hypothesis.  Rest = R14.
// ---------------------------------------------------------------------------

#define B_  4
#define S_  1024
#define D_  1024
#define H_  16
#define HS_ 64
#define L_  4
#define DFF_ 4096
#define V_  32000
#define M_  (B_ * S_)
#define MD_ ((size_t)M_ * D_)
#define EPS_ 1e-5f
#define SCALE_ 0.03125f        // D^-0.5 = 1/32 (reference uses d_model)

// ------------------------- scratch -----------------------------------------
__device__ float g_x  [M_ * D_];
__device__ float g_xn [M_ * D_];

__device__ __align__(16) __half g_qkvh[3 * M_ * D_];
__device__ __align__(16) __half g_ah[M_ * D_];
__device__ __align__(16) __half g_hh[M_ * DFF_];

#define DD_      ((size_t)D_ * D_)
#define WQ_OFF_  ((size_t)0)
#define WK_OFF_  (4 * DD_)
#define WV_OFF_  (8 * DD_)
#define WO_OFF_  (12 * DD_)
#define W1_OFF_  (16 * DD_)
#define W2_OFF_  (32 * DD_)
#define WH_OFF_  (48 * DD_)
#define WT_TOT_  (48 * DD_ + (size_t)D_ * V_)
__device__ __align__(16) __half g_wh[WT_TOT_];

// ------------------------- PTX helpers --------------------------------------
__device__ __forceinline__ uint32_t smem_u32(const void* p) {
    uint32_t a;
    asm("{ .reg .u64 t; cvta.to.shared.u64 t, %1; cvt.u32.u64 %0, t; }"
        : "=r"(a) : "l"(p));
    return a;
}
#define CP16(dst, src) \
    asm volatile("cp.async.cg.shared.global [%0], [%1], 16;" :: "r"(dst), "l"(src))
#define CPCOMMIT() asm volatile("cp.async.commit_group;" ::: "memory")
#define CPWAIT0()  asm volatile("cp.async.wait_group 0;" ::: "memory")
#define CPWAIT1()  asm volatile("cp.async.wait_group 1;" ::: "memory")

__device__ __forceinline__ void ldsm4(uint32_t* r, uint32_t addr) {
    asm volatile("ldmatrix.sync.aligned.m8n8.x4.shared.b16 {%0,%1,%2,%3}, [%4];"
        : "=r"(r[0]), "=r"(r[1]), "=r"(r[2]), "=r"(r[3]) : "r"(addr));
}
__device__ __forceinline__ void ldsm4t(uint32_t* r, uint32_t addr) {
    asm volatile("ldmatrix.sync.aligned.m8n8.x4.trans.shared.b16 {%0,%1,%2,%3}, [%4];"
        : "=r"(r[0]), "=r"(r[1]), "=r"(r[2]), "=r"(r[3]) : "r"(addr));
}
__device__ __forceinline__ void ldsm2(uint32_t* r, uint32_t addr) {
    asm volatile("ldmatrix.sync.aligned.m8n8.x2.shared.b16 {%0,%1}, [%2];"
        : "=r"(r[0]), "=r"(r[1]) : "r"(addr));
}
__device__ __forceinline__ void ldsm2t(uint32_t* r, uint32_t addr) {
    asm volatile("ldmatrix.sync.aligned.m8n8.x2.trans.shared.b16 {%0,%1}, [%2];"
        : "=r"(r[0]), "=r"(r[1]) : "r"(addr));
}
// fp32-accumulate mma (attention)
__device__ __forceinline__ void mma16816(float* d, const uint32_t* a, const uint32_t* b) {
    asm volatile(
        "mma.sync.aligned.m16n8k16.row.col.f32.f16.f16.f32 "
        "{%0,%1,%2,%3}, {%4,%5,%6,%7}, {%8,%9}, {%0,%1,%2,%3};"
        : "+f"(d[0]), "+f"(d[1]), "+f"(d[2]), "+f"(d[3])
        : "r"(a[0]), "r"(a[1]), "r"(a[2]), "r"(a[3]), "r"(b[0]), "r"(b[1]));
}
// fp16-accumulate mma (GEMM chunks)
__device__ __forceinline__ void mma16816h(uint32_t* d, const uint32_t* a, const uint32_t* b) {
    asm volatile(
        "mma.sync.aligned.m16n8k16.row.col.f16.f16.f16.f16 "
        "{%0,%1}, {%2,%3,%4,%5}, {%6,%7}, {%0,%1};"
        : "+r"(d[0]), "+r"(d[1])
        : "r"(a[0]), "r"(a[1]), "r"(a[2]), "r"(a[3]), "r"(b[0]), "r"(b[1]));
}

__device__ __forceinline__ uint32_t pack2h(float a, float b) {
    __half2 h = __halves2half2(__float2half_rn(a), __float2half_rn(b));
    return *(uint32_t*)&h;
}

// block reduction over 256 threads via warp shuffles
__device__ __forceinline__ float blk_sum(float v, float* ws, int tid) {
    #pragma unroll
    for (int st = 16; st > 0; st >>= 1)
        v += __shfl_xor_sync(0xffffffff, v, st);
    if ((tid & 31) == 0) ws[tid >> 5] = v;
    __syncthreads();
    if (tid < 32) {
        float w = (tid < 8) ? ws[tid] : 0.0f;
        #pragma unroll
        for (int st = 4; st > 0; st >>= 1)
            w += __shfl_xor_sync(0xffffffff, w, st);
        if (tid == 0) ws[0] = w;
    }
    __syncthreads();
    return ws[0];
}

// ------------------------- LN core ------------------------------------------
__device__ __forceinline__ void ln_finish(
    float4 xv, int tid, size_t i,
    const float4* __restrict__ g, const float4* __restrict__ bb,
    float4* __restrict__ y, uint2* __restrict__ oh,
    float* ws1, float* ws2)
{
    float s = xv.x + xv.y + xv.z + xv.w;
    float mu = blk_sum(s, ws1, tid) * (1.0f / D_);

    float dx = xv.x - mu, dy = xv.y - mu, dz = xv.z - mu, dw = xv.w - mu;
    float s2 = dx * dx + dy * dy + dz * dz + dw * dw;
    float var = blk_sum(s2, ws2, tid) * (1.0f / D_);
    float inv = rsqrtf(var + EPS_);

    float4 gv = g[tid], bv = bb[tid];
    float4 o;
    o.x = dx * inv * gv.x + bv.x;
    o.y = dy * inv * gv.y + bv.y;
    o.z = dz * inv * gv.z + bv.z;
    o.w = dw * inv * gv.w + bv.w;
    y[i] = o;

    uint2 hp;
    hp.x = pack2h(o.x, o.y);
    hp.y = pack2h(o.z, o.w);
    oh[i] = hp;
}

__global__ __launch_bounds__(256) void layernorm_k(
    const float4* __restrict__ x, const float4* __restrict__ g,
    const float4* __restrict__ bb, float4* __restrict__ y,
    uint2* __restrict__ oh)
{
    __shared__ float ws1[8], ws2[8];
    int row = blockIdx.x, tid = threadIdx.x;
    size_t i = (size_t)row * 256 + tid;
    float4 xv = x[i];
    ln_finish(xv, tid, i, g, bb, y, oh, ws1, ws2);
}

__global__ __launch_bounds__(256) void embed_ln_k(
    const int* __restrict__ idx, const float4* __restrict__ tok,
    const float4* __restrict__ pos,
    const float4* __restrict__ g, const float4* __restrict__ bb,
    float4* __restrict__ y, uint2* __restrict__ oh)
{
    __shared__ float ws1[8], ws2[8];
    int row = blockIdx.x, tid = threadIdx.x;
    int s   = row & (S_ - 1);
    int t   = idx[row];
    float4 tv = tok[(size_t)t * 256 + tid];
    float4 pv = pos[(size_t)s * 256 + tid];
    float4 xv;
    xv.x = tv.x + pv.x; xv.y = tv.y + pv.y;
    xv.z = tv.z + pv.z; xv.w = tv.w + pv.w;
    size_t i = (size_t)row * 256 + tid;
    ln_finish(xv, tid, i, g, bb, y, oh, ws1, ws2);
}

// ------------------------- fp32 -> fp16 (weights) ----------------------------
__global__ __launch_bounds__(256) void wsplit_k(
    const float4* __restrict__ x, uint4* __restrict__ h, int n4)
{
    int npair = n4 >> 1;
    int quarter = npair >> 2;
    int i = blockIdx.x * 256 + threadIdx.x;
    if (i >= quarter) return;
    #pragma unroll
    for (int m = 0; m < 4; m++) {
        int p = i + m * quarter;
        float4 v0 = x[2 * p];
        float4 v1 = x[2 * p + 1];
        uint4 o;
        o.x = pack2h(v0.x, v0.y);
        o.y = pack2h(v0.z, v0.w);
        o.z = pack2h(v1.x, v1.y);
        o.w = pack2h(v1.z, v1.w);
        h[p] = o;
    }
}

// ------------------------- mma.sync GEMM (f16 chunk accum) -------------------
#define ATILEB_ 16384
#define BTILEB_ 32768
#define BUFB_   (ATILEB_ + BTILEB_)        // 48 KB
#define SMTOT_  (2 * BUFB_)                // 96 KB

template<bool BIAS, bool RES, bool RELU, bool OHALF>
__global__ __launch_bounds__(256, 1) void mma_gemm_k(
    int M, int N, int K,
    const __half* __restrict__ Ah,
    const __half* __restrict__ Bw,
    const float* __restrict__ bias, const float* __restrict__ res,
    float* __restrict__ C,
    __half2* __restrict__ Oh,
    size_t bzS, size_t czS, size_t ozS)
{
    extern __shared__ char smem[];
    const uint32_t sb = smem_u32(smem);
    const int tid = threadIdx.x, wid = tid >> 5, lane = tid & 31;
    const int mb = blockIdx.x, nb = blockIdx.y;
    Bw += blockIdx.z * bzS;
    C  += blockIdx.z * czS;
    if (OHALF) Oh += blockIdx.z * ozS;
    const size_t ar0 = (size_t)mb * 128, bc0 = (size_t)nb * 256;
    const int wm = (wid >> 2) * 64, wn = (wid & 3) * 64;

    float acc[4][8][4];
    #pragma unroll
    for (int i = 0; i < 4; i++)
        #pragma unroll
        for (int j = 0; j < 8; j++)
            #pragma unroll
            for (int e = 0; e < 4; e++) acc[i][j][e] = 0.0f;

    const int nch = K >> 6;

    auto fill = [&](int buf, int c) {
        const size_t kof = (size_t)c << 6;
        const uint32_t bb = sb + buf * BUFB_;
        #pragma unroll
        for (int i = 0; i < 4; i++) {
            int id = tid + 256 * i;
            int r  = id >> 3;
            int cx = id & 7;
            uint32_t so = (uint32_t)(r * 128 + cx * 16);
            so ^= (so >> 3) & 0x70;
            size_t ai = (ar0 + r) * (size_t)K + kof + cx * 8;
            CP16(bb + so, Ah + ai);
        }
        #pragma unroll
        for (int i = 0; i < 8; i++) {
            int id = tid + 256 * i;
            int kr = id >> 5;
            int cx = id & 31;
            uint32_t so = (uint32_t)(kr * 512 + ((cx ^ (kr & 31)) * 16));
            size_t bi = (kof + kr) * (size_t)N + bc0 + cx * 8;
            CP16(bb + ATILEB_ + so, Bw + bi);
        }
    };

    fill(0, 0); CPCOMMIT();

    uint32_t fa[4][4], fb[8][2], d16[4][8][2];
    const int arow = wm + (lane & 15);
    const int akb  = (lane >> 4) * 16;
    const int krl  = lane & 15;
    const int nsel = lane >> 4;

    for (int c = 0; c < nch; c++) {
        if (c + 1 < nch) { fill((c + 1) & 1, c + 1); CPCOMMIT(); CPWAIT1(); }
        else             { CPWAIT0(); }
        __syncthreads();

        // zero chunk-local f16 accumulators
        #pragma unroll
        for (int i = 0; i < 4; i++)
            #pragma unroll
            for (int j = 0; j < 8; j++) { d16[i][j][0] = 0u; d16[i][j][1] = 0u; }

        const uint32_t base = sb + (c & 1) * BUFB_;
        #pragma unroll
        for (int ks = 0; ks < 4; ks++) {
            #pragma unroll
            for (int i = 0; i < 4; i++) {
                uint32_t so = (uint32_t)((arow + i * 16) * 128 + ks * 32 + akb);
                so ^= (so >> 3) & 0x70;
                ldsm4(fa[i], base + so);
            }
            const uint32_t krow = (uint32_t)(ks * 16 + krl);
            #pragma unroll
            for (int j2 = 0; j2 < 4; j2++) {
                uint32_t cx = (uint32_t)((wn >> 3) + 2 * j2 + nsel);
                uint32_t so = krow * 512 + ((cx ^ (krow & 31)) * 16);
                uint32_t r[4];
                ldsm4t(r, base + ATILEB_ + so);
                fb[2 * j2 + 0][0] = r[0]; fb[2 * j2 + 0][1] = r[1];
                fb[2 * j2 + 1][0] = r[2]; fb[2 * j2 + 1][1] = r[3];
            }
            #pragma unroll
            for (int i = 0; i < 4; i++)
                #pragma unroll
                for (int j = 0; j < 8; j++)
                    mma16816h(d16[i][j], fa[i], fb[j]);
        }
        // promote chunk result to fp32
        #pragma unroll
        for (int i = 0; i < 4; i++)
            #pragma unroll
            for (int j = 0; j < 8; j++) {
                float2 f0 = __half22float2(*(__half2*)&d16[i][j][0]);
                float2 f1 = __half22float2(*(__half2*)&d16[i][j][1]);
                acc[i][j][0] += f0.x; acc[i][j][1] += f0.y;
                acc[i][j][2] += f1.x; acc[i][j][3] += f1.y;
            }
        __syncthreads();
    }

    const int g  = lane >> 2, tg = lane & 3;
    const size_t row0 = ar0 + wm, col0 = bc0 + wn;
    #pragma unroll
    for (int i = 0; i < 4; i++) {
        #pragma unroll
        for (int j = 0; j < 8; j++) {
            size_t col = col0 + j * 8 + tg * 2;
            float bx = 0.0f, by = 0.0f;
            if (BIAS) { bx = bias[col]; by = bias[col + 1]; }
            #pragma unroll
            for (int half = 0; half < 2; half++) {
                size_t row = row0 + i * 16 + g + half * 8;
                float vx = acc[i][j][2 * half + 0] + bx;
                float vy = acc[i][j][2 * half + 1] + by;
                size_t gi = row * (size_t)N + col;
                if (RES) { vx += res[gi]; vy += res[gi + 1]; }
                if (RELU) { vx = fmaxf(vx, 0.0f); vy = fmaxf(vy, 0.0f); }
                if (OHALF) {
                    Oh[gi >> 1] = __halves2half2(__float2half_rn(vx),
                                                 __float2half_rn(vy));
                } else {
                    float2 o; o.x = vx; o.y = vy;
                    *(float2*)(C + gi) = o;
                }
            }
        }
    }
}

// ------------------------- tensor-core attention -----------------------------
#define QT_    16
#define NTL_   128
#define SROW_  1032
#define SBY_   (QT_ * SROW_ * 4)
#define P_OFF_ SBY_
#define Q_OFF_ (P_OFF_ + QT_ * 2048)
#define KV_OFF_ (Q_OFF_ + 2048)
#define KVB_   16384
#define RINV_OFF_ (KV_OFF_ + 2 * KVB_)
#define ATT_SM_ (RINV_OFF_ + 64)

__global__ __launch_bounds__(256, 1) void attn_tc_k(
    const __half* __restrict__ qkvh, __half* __restrict__ oh)
{
    extern __shared__ char smc[];
    const uint32_t sb = smem_u32(smc);
    float* S    = (float*)smc;
    float* Rinv = (float*)(smc + RINV_OFF_);

    const int tid = threadIdx.x, wid = tid >> 5, lane = tid & 31;
    const int qt = (int)gridDim.x - 1 - (int)blockIdx.x;
    const int h = blockIdx.y, b = blockIdx.z;
    const int q0 = qt * QT_;
    const int nt = (q0 + QT_ + NTL_ - 1) / NTL_;

    const size_t hrow = (size_t)H_ * HS_;
    const __half* qg = qkvh + ((size_t)b * S_ + q0) * hrow + h * HS_;
    const __half* kg = qkvh + MD_     + (size_t)b * S_ * hrow + h * HS_;
    const __half* vg = qkvh + 2 * MD_ + (size_t)b * S_ * hrow + h * HS_;

    auto stageKV = [&](uint32_t dst, const __half* src, int t) {
        int j0 = t * NTL_;
        #pragma unroll
        for (int i = 0; i < 4; i++) {
            int id = tid + 256 * i;
            int r  = id >> 3;
            int cx = id & 7;
            uint32_t so = (uint32_t)(r * 128 + cx * 16);
            so ^= (so >> 3) & 0x70;
            CP16(dst + so, src + (size_t)(j0 + r) * hrow + cx * 8);
        }
    };

    if (tid < 128) {
        int r = tid >> 3, cx = tid & 7;
        uint32_t so = (uint32_t)(r * 128 + cx * 16);
        so ^= (so >> 3) & 0x70;
        CP16(sb + Q_OFF_ + so, qg + (size_t)r * hrow + cx * 8);
    }
    CPCOMMIT();
    stageKV(sb + KV_OFF_, kg, 0); CPCOMMIT();
    CPWAIT1();
    __syncthreads();

    uint32_t qf[4][4];
    {
        const int arow = lane & 15;
        const int akb  = (lane >> 4) * 16;
        #pragma unroll
        for (int ks = 0; ks < 4; ks++) {
            uint32_t so = (uint32_t)(arow * 128 + ks * 32 + akb);
            so ^= (so >> 3) & 0x70;
            ldsm4(qf[ks], sb + Q_OFF_ + so);
        }
    }

    for (int t = 0; t < nt; t++) {
        if (t + 1 < nt) { stageKV(sb + KV_OFF_ + ((t + 1) & 1) * KVB_, kg, t + 1); CPCOMMIT(); CPWAIT1(); }
        else            { CPWAIT0(); }
        __syncthreads();

        const uint32_t kb = sb + KV_OFF_ + (t & 1) * KVB_;
        #pragma unroll
        for (int sub = 0; sub < 2; sub++) {
            int n0 = (2 * wid + sub) * 8;
            float acc[4] = {0.0f, 0.0f, 0.0f, 0.0f};
            #pragma unroll
            for (int ks = 0; ks < 4; ks++) {
                uint32_t bf[2];
                uint32_t so = (uint32_t)((n0 + (lane & 7)) * 128 + ks * 32 + ((lane >> 3) & 1) * 16);
                so ^= (so >> 3) & 0x70;
                ldsm2(bf, kb + so);
                mma16816(acc, qf[ks], bf);
            }
            int g = lane >> 2, tg = lane & 3;
            int col = t * NTL_ + n0 + tg * 2;
            S[g * SROW_ + col]           = acc[0] * SCALE_;
            S[g * SROW_ + col + 1]       = acc[1] * SCALE_;
            S[(g + 8) * SROW_ + col]     = acc[2] * SCALE_;
            S[(g + 8) * SROW_ + col + 1] = acc[3] * SCALE_;
        }
        __syncthreads();
    }

    // V tile 0 prefetch overlaps the softmax below
    stageKV(sb + KV_OFF_, vg, 0); CPCOMMIT();

    {
        const int jmax = nt * NTL_;
        __half* P = (__half*)(smc + P_OFF_);
        #pragma unroll
        for (int qq = 0; qq < 2; qq++) {
            int r  = 2 * wid + qq;
            int nq = q0 + r + 1;
            float m = -1e30f;
            for (int j = lane; j < nq; j += 32) m = fmaxf(m, S[r * SROW_ + j]);
            #pragma unroll
            for (int st = 16; st > 0; st >>= 1)
                m = fmaxf(m, __shfl_xor_sync(0xffffffff, m, st));
            float sum = 0.0f;
            for (int j = lane; j < jmax; j += 32) {
                float e = 0.0f;
                if (j < nq) { e = __expf(S[r * SROW_ + j] - m); sum += e; }
                int ch = j >> 3;
                uint32_t off = (uint32_t)(r * 2048 + ((ch ^ (r & 7)) * 16) + (j & 7) * 2);
                *(__half*)((char*)P + off) = __float2half_rn(e);
            }
            #pragma unroll
            for (int st = 16; st > 0; st >>= 1)
                sum += __shfl_xor_sync(0xffffffff, sum, st);
            if (lane == 0) Rinv[r] = 1.0f / sum;
        }
    }
    __syncthreads();

    float oacc[4] = {0.0f, 0.0f, 0.0f, 0.0f};
    for (int t = 0; t < nt; t++) {
        if (t + 1 < nt) { stageKV(sb + KV_OFF_ + ((t + 1) & 1) * KVB_, vg, t + 1); CPCOMMIT(); CPWAIT1(); }
        else            { CPWAIT0(); }
        __syncthreads();

        const uint32_t vb = sb + KV_OFF_ + (t & 1) * KVB_;
        #pragma unroll
        for (int ks = 0; ks < 8; ks++) {
            uint32_t pf[4];
            {
                int r  = lane & 15;
                int ch = t * 16 + 2 * ks + (lane >> 4);
                uint32_t addr = (uint32_t)(P_OFF_ + r * 2048 + ((ch ^ (r & 7)) * 16));
                ldsm4(pf, sb + addr);
            }
            uint32_t vf[2];
            {
                int kr = ks * 16 + (lane & 15);
                int cx = wid;
                uint32_t so = (uint32_t)(kr * 128 + ((cx ^ (kr & 7)) * 16));
                ldsm2t(vf, vb + so);
            }
            mma16816(oacc, pf, vf);
        }
        __syncthreads();
    }

    {
        int g = lane >> 2, tg = lane & 3;
        int col = wid * 8 + tg * 2;
        #pragma unroll
        for (int half = 0; half < 2; half++) {
            int row = g + half * 8;
            float rv = Rinv[row];
            __half2 o = __halves2half2(__float2half_rn(oacc[2 * half + 0] * rv),
                                       __float2half_rn(oacc[2 * half + 1] * rv));
            *(__half2*)(oh + ((size_t)b * S_ + q0 + row) * hrow + h * HS_ + col) = o;
        }
    }
}

// ------------------------- driver -------------------------------------------
static cudaStream_t g_s2 = nullptr;
static cudaEvent_t  g_evFork = nullptr, g_evJ0 = nullptr, g_evJ1 = nullptr;

static inline void wsplit_on(cudaStream_t st, const float* src, __half* dst, size_t nfloat)
{
    int n4 = (int)(nfloat / 4);
    int quarter = (n4 >> 1) >> 2;
    wsplit_k<<<(quarter + 255) / 256, 256, 0, st>>>(
        (const float4*)src, (uint4*)dst, n4);
}

extern "C" void kernel_launch(void* const* d_in, const int* in_sizes, int n_in,
                              void* d_out, int out_size)
{
    const int*   idx   = (const int*)  d_in[0];
    const float* tok   = (const float*)d_in[1];
    const float* pos   = (const float*)d_in[2];
    const float* ln1g  = (const float*)d_in[3];
    const float* ln1b  = (const float*)d_in[4];
    const float* ln2g  = (const float*)d_in[5];
    const float* ln2b  = (const float*)d_in[6];
    const float* wq    = (const float*)d_in[7];
    const float* wk    = (const float*)d_in[8];
    const float* wv    = (const float*)d_in[9];
    const float* wo    = (const float*)d_in[10];
    const float* bo    = (const float*)d_in[11];
    const float* w1    = (const float*)d_in[12];
    const float* b1    = (const float*)d_in[13];
    const float* w2    = (const float*)d_in[14];
    const float* b2    = (const float*)d_in[15];
    const float* lnfg  = (const float*)d_in[16];
    const float* lnfb  = (const float*)d_in[17];
    const float* whead = (const float*)d_in[18];
    const float* bhead = (const float*)d_in[19];
    float* out = (float*)d_out;

    float *x, *xn;
    __half *qkvh, *ah, *hh, *wh;
    cudaGetSymbolAddress((void**)&x,    g_x);
    cudaGetSymbolAddress((void**)&xn,   g_xn);
    cudaGetSymbolAddress((void**)&qkvh, g_qkvh);
    cudaGetSymbolAddress((void**)&ah,   g_ah);
    cudaGetSymbolAddress((void**)&hh,   g_hh);
    cudaGetSymbolAddress((void**)&wh,   g_wh);

    cudaFuncSetAttribute(mma_gemm_k<false,false,false,true>,  cudaFuncAttributeMaxDynamicSharedMemorySize, SMTOT_);
    cudaFuncSetAttribute(mma_gemm_k<true,true,false,false>,   cudaFuncAttributeMaxDynamicSharedMemorySize, SMTOT_);
    cudaFuncSetAttribute(mma_gemm_k<true,false,true,true>,    cudaFuncAttributeMaxDynamicSharedMemorySize, SMTOT_);
    cudaFuncSetAttribute(mma_gemm_k<true,false,false,false>,  cudaFuncAttributeMaxDynamicSharedMemorySize, SMTOT_);
    cudaFuncSetAttribute(attn_tc_k, cudaFuncAttributeMaxDynamicSharedMemorySize, ATT_SM_);

    if (!g_s2) {
        cudaStreamCreateWithFlags(&g_s2, cudaStreamNonBlocking);
        cudaEventCreateWithFlags(&g_evFork, cudaEventDisableTiming);
        cudaEventCreateWithFlags(&g_evJ0,   cudaEventDisableTiming);
        cudaEventCreateWithFlags(&g_evJ1,   cudaEventDisableTiming);
    }

    dim3 blk(256);

    // ---- fork ALL weight conversion onto the side stream ----
    cudaEventRecord(g_evFork, 0);
    cudaStreamWaitEvent(g_s2, g_evFork, 0);
    wsplit_on(g_s2, wq, wh + WQ_OFF_, DD_);
    wsplit_on(g_s2, wk, wh + WK_OFF_, DD_);
    wsplit_on(g_s2, wv, wh + WV_OFF_, DD_);
    wsplit_on(g_s2, wo, wh + WO_OFF_, DD_);
    wsplit_on(g_s2, w1, wh + W1_OFF_, 4 * DD_);
    wsplit_on(g_s2, w2, wh + W2_OFF_, 4 * DD_);
    cudaEventRecord(g_evJ0, g_s2);
    wsplit_on(g_s2, wq + DD_,     wh + WQ_OFF_ + DD_,     3 * DD_);
    wsplit_on(g_s2, wk + DD_,     wh + WK_OFF_ + DD_,     3 * DD_);
    wsplit_on(g_s2, wv + DD_,     wh + WV_OFF_ + DD_,     3 * DD_);
    wsplit_on(g_s2, wo + DD_,     wh + WO_OFF_ + DD_,     3 * DD_);
    wsplit_on(g_s2, w1 + 4 * DD_, wh + W1_OFF_ + 4 * DD_, 12 * DD_);
    wsplit_on(g_s2, w2 + 4 * DD_, wh + W2_OFF_ + 4 * DD_, 12 * DD_);
    wsplit_on(g_s2, whead,        wh + WH_OFF_,           (size_t)D_ * V_);
    cudaEventRecord(g_evJ1, g_s2);

    // ---- layer 0 front: fused embed + LN1 ----
    embed_ln_k<<<M_, blk>>>(idx, (const float4*)tok, (const float4*)pos,
                            (const float4*)ln1g, (const float4*)ln1b,
                            (float4*)xn, (uint2*)ah);

    for (int l = 0; l < L_; l++) {
        if (l == 0) cudaStreamWaitEvent(0, g_evJ0, 0);
        if (l == 1) cudaStreamWaitEvent(0, g_evJ1, 0);

        size_t oq = WQ_OFF_ + (size_t)l * DD_;
        size_t oo = WO_OFF_ + (size_t)l * DD_;
        size_t o1 = W1_OFF_ + (size_t)l * 4 * DD_;
        size_t o2 = W2_OFF_ + (size_t)l * 4 * DD_;

        if (l > 0)
            layernorm_k<<<M_, blk>>>((const float4*)x, (const float4*)(ln1g + l * D_),
                                     (const float4*)(ln1b + l * D_), (float4*)xn,
                                     (uint2*)ah);

        // fused QKV -> fp16 qkv slabs
        mma_gemm_k<false,false,false,true><<<dim3(M_/128, D_/256, 3), blk, SMTOT_>>>(
            M_, D_, D_, ah, wh + oq, nullptr, nullptr, nullptr,
            (__half2*)qkvh, 4 * DD_, 0, MD_ / 2);

        attn_tc_k<<<dim3(S_ / QT_, H_, B_), 256, ATT_SM_>>>(qkvh, ah);

        // x = xn + att @ wo + bo
        mma_gemm_k<true,true,false,false><<<dim3(M_/128, D_/256), blk, SMTOT_>>>(
            M_, D_, D_, ah, wh + oo, bo + l * D_, xn, x,
            nullptr, 0, 0, 0);

        layernorm_k<<<M_, blk>>>((const float4*)x, (const float4*)(ln2g + l * D_),
                                 (const float4*)(ln2b + l * D_), (float4*)xn,
                                 (uint2*)ah);

        // h = relu(xn @ w1 + b1)  -> fp16 directly
        mma_gemm_k<true,false,true,true><<<dim3(M_/128, DFF_/256), blk, SMTOT_>>>(
            M_, DFF_, D_, ah, wh + o1,
            b1 + (size_t)l * DFF_, nullptr, nullptr,
            (__half2*)hh, 0, 0, 0);

        // x = xn + h @ w2 + b2
        mma_gemm_k<true,true,false,false><<<dim3(M_/128, D_/256), blk, SMTOT_>>>(
            M_, D_, DFF_, hh, wh + o2,
            b2 + l * D_, xn, x, nullptr, 0, 0, 0);
    }

    layernorm_k<<<M_, blk>>>((const float4*)x, (const float4*)lnfg,
                             (const float4*)lnfb, (float4*)xn,
                             (uint2*)ah);

    // logits = xn @ w_head + b_head
    mma_gemm_k<true,false,false,false><<<dim3(M_/128, V_/256), blk, SMTOT_>>>(
        M_, V_, D_, ah, wh + WH_OFF_,
        bhead, nullptr, out, nullptr, 0, 0, 0);
}

// round 16
// speedup vs baseline: 1.1700x; 1.1700x over previous
#include <cuda_runtime.h>
#include <cuda_fp16.h>
#include <cstdint>
#include <math.h>

// ---------------------------------------------------------------------------
// MinGPT forward.  B=4, S=1024, D=1024, H=16, HS=64, L=4, DFF=4096, V=32000.
// Round 16: R14 configuration restored (fp32-accum GEMM, 3-stage pipeline)
// + final LN skips its dead fp32 output.
// ---------------------------------------------------------------------------

#define B_  4
#define S_  1024
#define D_  1024
#define H_  16
#define HS_ 64
#define L_  4
#define DFF_ 4096
#define V_  32000
#define M_  (B_ * S_)
#define MD_ ((size_t)M_ * D_)
#define EPS_ 1e-5f
#define SCALE_ 0.03125f        // D^-0.5 = 1/32 (reference uses d_model)

// ------------------------- scratch -----------------------------------------
__device__ float g_x  [M_ * D_];
__device__ float g_xn [M_ * D_];

__device__ __align__(16) __half g_qkvh[3 * M_ * D_];
__device__ __align__(16) __half g_ah[M_ * D_];
__device__ __align__(16) __half g_hh[M_ * DFF_];

#define DD_      ((size_t)D_ * D_)
#define WQ_OFF_  ((size_t)0)
#define WK_OFF_  (4 * DD_)
#define WV_OFF_  (8 * DD_)
#define WO_OFF_  (12 * DD_)
#define W1_OFF_  (16 * DD_)
#define W2_OFF_  (32 * DD_)
#define WH_OFF_  (48 * DD_)
#define WT_TOT_  (48 * DD_ + (size_t)D_ * V_)
__device__ __align__(16) __half g_wh[WT_TOT_];

// ------------------------- PTX helpers --------------------------------------
__device__ __forceinline__ uint32_t smem_u32(const void* p) {
    uint32_t a;
    asm("{ .reg .u64 t; cvta.to.shared.u64 t, %1; cvt.u32.u64 %0, t; }"
        : "=r"(a) : "l"(p));
    return a;
}
#define CP16(dst, src) \
    asm volatile("cp.async.cg.shared.global [%0], [%1], 16;" :: "r"(dst), "l"(src))
#define CPCOMMIT() asm volatile("cp.async.commit_group;" ::: "memory")
#define CPWAIT0()  asm volatile("cp.async.wait_group 0;" ::: "memory")
#define CPWAIT1()  asm volatile("cp.async.wait_group 1;" ::: "memory")
#define CPWAIT2()  asm volatile("cp.async.wait_group 2;" ::: "memory")

__device__ __forceinline__ void ldsm4(uint32_t* r, uint32_t addr) {
    asm volatile("ldmatrix.sync.aligned.m8n8.x4.shared.b16 {%0,%1,%2,%3}, [%4];"
        : "=r"(r[0]), "=r"(r[1]), "=r"(r[2]), "=r"(r[3]) : "r"(addr));
}
__device__ __forceinline__ void ldsm4t(uint32_t* r, uint32_t addr) {
    asm volatile("ldmatrix.sync.aligned.m8n8.x4.trans.shared.b16 {%0,%1,%2,%3}, [%4];"
        : "=r"(r[0]), "=r"(r[1]), "=r"(r[2]), "=r"(r[3]) : "r"(addr));
}
__device__ __forceinline__ void ldsm2(uint32_t* r, uint32_t addr) {
    asm volatile("ldmatrix.sync.aligned.m8n8.x2.shared.b16 {%0,%1}, [%2];"
        : "=r"(r[0]), "=r"(r[1]) : "r"(addr));
}
__device__ __forceinline__ void ldsm2t(uint32_t* r, uint32_t addr) {
    asm volatile("ldmatrix.sync.aligned.m8n8.x2.trans.shared.b16 {%0,%1}, [%2];"
        : "=r"(r[0]), "=r"(r[1]) : "r"(addr));
}
__device__ __forceinline__ void mma16816(float* d, const uint32_t* a, const uint32_t* b) {
    asm volatile(
        "mma.sync.aligned.m16n8k16.row.col.f32.f16.f16.f32 "
        "{%0,%1,%2,%3}, {%4,%5,%6,%7}, {%8,%9}, {%0,%1,%2,%3};"
        : "+f"(d[0]), "+f"(d[1]), "+f"(d[2]), "+f"(d[3])
        : "r"(a[0]), "r"(a[1]), "r"(a[2]), "r"(a[3]), "r"(b[0]), "r"(b[1]));
}

__device__ __forceinline__ uint32_t pack2h(float a, float b) {
    __half2 h = __halves2half2(__float2half_rn(a), __float2half_rn(b));
    return *(uint32_t*)&h;
}

// block reduction over 256 threads via warp shuffles
__device__ __forceinline__ float blk_sum(float v, float* ws, int tid) {
    #pragma unroll
    for (int st = 16; st > 0; st >>= 1)
        v += __shfl_xor_sync(0xffffffff, v, st);
    if ((tid & 31) == 0) ws[tid >> 5] = v;
    __syncthreads();
    if (tid < 32) {
        float w = (tid < 8) ? ws[tid] : 0.0f;
        #pragma unroll
        for (int st = 4; st > 0; st >>= 1)
            w += __shfl_xor_sync(0xffffffff, w, st);
        if (tid == 0) ws[0] = w;
    }
    __syncthreads();
    return ws[0];
}

// ------------------------- LN core ------------------------------------------
template<bool WRITEY>
__device__ __forceinline__ void ln_finish(
    float4 xv, int tid, size_t i,
    const float4* __restrict__ g, const float4* __restrict__ bb,
    float4* __restrict__ y, uint2* __restrict__ oh,
    float* ws1, float* ws2)
{
    float s = xv.x + xv.y + xv.z + xv.w;
    float mu = blk_sum(s, ws1, tid) * (1.0f / D_);

    float dx = xv.x - mu, dy = xv.y - mu, dz = xv.z - mu, dw = xv.w - mu;
    float s2 = dx * dx + dy * dy + dz * dz + dw * dw;
    float var = blk_sum(s2, ws2, tid) * (1.0f / D_);
    float inv = rsqrtf(var + EPS_);

    float4 gv = g[tid], bv = bb[tid];
    float4 o;
    o.x = dx * inv * gv.x + bv.x;
    o.y = dy * inv * gv.y + bv.y;
    o.z = dz * inv * gv.z + bv.z;
    o.w = dw * inv * gv.w + bv.w;
    if (WRITEY) y[i] = o;

    uint2 hp;
    hp.x = pack2h(o.x, o.y);
    hp.y = pack2h(o.z, o.w);
    oh[i] = hp;
}

template<bool WRITEY>
__global__ __launch_bounds__(256) void layernorm_k(
    const float4* __restrict__ x, const float4* __restrict__ g,
    const float4* __restrict__ bb, float4* __restrict__ y,
    uint2* __restrict__ oh)
{
    __shared__ float ws1[8], ws2[8];
    int row = blockIdx.x, tid = threadIdx.x;
    size_t i = (size_t)row * 256 + tid;
    float4 xv = x[i];
    ln_finish<WRITEY>(xv, tid, i, g, bb, y, oh, ws1, ws2);
}

__global__ __launch_bounds__(256) void embed_ln_k(
    const int* __restrict__ idx, const float4* __restrict__ tok,
    const float4* __restrict__ pos,
    const float4* __restrict__ g, const float4* __restrict__ bb,
    float4* __restrict__ y, uint2* __restrict__ oh)
{
    __shared__ float ws1[8], ws2[8];
    int row = blockIdx.x, tid = threadIdx.x;
    int s   = row & (S_ - 1);
    int t   = idx[row];
    float4 tv = tok[(size_t)t * 256 + tid];
    float4 pv = pos[(size_t)s * 256 + tid];
    float4 xv;
    xv.x = tv.x + pv.x; xv.y = tv.y + pv.y;
    xv.z = tv.z + pv.z; xv.w = tv.w + pv.w;
    size_t i = (size_t)row * 256 + tid;
    ln_finish<true>(xv, tid, i, g, bb, y, oh, ws1, ws2);
}

// ------------------------- fp32 -> fp16 (weights) ----------------------------
__global__ __launch_bounds__(256) void wsplit_k(
    const float4* __restrict__ x, uint4* __restrict__ h, int n4)
{
    int npair = n4 >> 1;
    int quarter = npair >> 2;
    int i = blockIdx.x * 256 + threadIdx.x;
    if (i >= quarter) return;
    #pragma unroll
    for (int m = 0; m < 4; m++) {
        int p = i + m * quarter;
        float4 v0 = x[2 * p];
        float4 v1 = x[2 * p + 1];
        uint4 o;
        o.x = pack2h(v0.x, v0.y);
        o.y = pack2h(v0.z, v0.w);
        o.z = pack2h(v1.x, v1.y);
        o.w = pack2h(v1.z, v1.w);
        h[p] = o;
    }
}

// ------------------------- mma.sync GEMM (3-stage pipeline, fp32 accum) ------
#define ATILEB_ 16384
#define BTILEB_ 32768
#define BUFB_   (ATILEB_ + BTILEB_)        // 48 KB
#define SMTOT_  (3 * BUFB_)                // 144 KB

template<bool BIAS, bool RES, bool RELU, bool OHALF>
__global__ __launch_bounds__(256, 1) void mma_gemm_k(
    int M, int N, int K,
    const __half* __restrict__ Ah,
    const __half* __restrict__ Bw,
    const float* __restrict__ bias, const float* __restrict__ res,
    float* __restrict__ C,
    __half2* __restrict__ Oh,
    size_t bzS, size_t czS, size_t ozS)
{
    extern __shared__ char smem[];
    const uint32_t sb = smem_u32(smem);
    const int tid = threadIdx.x, wid = tid >> 5, lane = tid & 31;
    const int mb = blockIdx.x, nb = blockIdx.y;
    Bw += blockIdx.z * bzS;
    C  += blockIdx.z * czS;
    if (OHALF) Oh += blockIdx.z * ozS;
    const size_t ar0 = (size_t)mb * 128, bc0 = (size_t)nb * 256;
    const int wm = (wid >> 2) * 64, wn = (wid & 3) * 64;

    float acc[4][8][4];
    #pragma unroll
    for (int i = 0; i < 4; i++)
        #pragma unroll
        for (int j = 0; j < 8; j++)
            #pragma unroll
            for (int e = 0; e < 4; e++) acc[i][j][e] = 0.0f;

    const int nch = K >> 6;

    auto fill = [&](int buf, int c) {
        const size_t kof = (size_t)c << 6;
        const uint32_t bb = sb + buf * BUFB_;
        #pragma unroll
        for (int i = 0; i < 4; i++) {
            int id = tid + 256 * i;
            int r  = id >> 3;
            int cx = id & 7;
            uint32_t so = (uint32_t)(r * 128 + cx * 16);
            so ^= (so >> 3) & 0x70;
            size_t ai = (ar0 + r) * (size_t)K + kof + cx * 8;
            CP16(bb + so, Ah + ai);
        }
        #pragma unroll
        for (int i = 0; i < 8; i++) {
            int id = tid + 256 * i;
            int kr = id >> 5;
            int cx = id & 31;
            uint32_t so = (uint32_t)(kr * 512 + ((cx ^ (kr & 31)) * 16));
            size_t bi = (kof + kr) * (size_t)N + bc0 + cx * 8;
            CP16(bb + ATILEB_ + so, Bw + bi);
        }
    };

    fill(0, 0); CPCOMMIT();
    fill(1, 1); CPCOMMIT();

    uint32_t fa[4][4], fb[8][2];
    const int arow = wm + (lane & 15);
    const int akb  = (lane >> 4) * 16;
    const int krl  = lane & 15;
    const int nsel = lane >> 4;

    int buf = 0;
    for (int c = 0; c < nch; c++) {
        if (c + 2 < nch) {
            int nbuf = buf + 2; if (nbuf >= 3) nbuf -= 3;
            fill(nbuf, c + 2); CPCOMMIT(); CPWAIT2();
        } else if (c + 1 < nch) { CPWAIT1(); }
        else                    { CPWAIT0(); }
        __syncthreads();

        const uint32_t base = sb + buf * BUFB_;
        #pragma unroll
        for (int ks = 0; ks < 4; ks++) {
            #pragma unroll
            for (int i = 0; i < 4; i++) {
                uint32_t so = (uint32_t)((arow + i * 16) * 128 + ks * 32 + akb);
                so ^= (so >> 3) & 0x70;
                ldsm4(fa[i], base + so);
            }
            const uint32_t krow = (uint32_t)(ks * 16 + krl);
            #pragma unroll
            for (int j2 = 0; j2 < 4; j2++) {
                uint32_t cx = (uint32_t)((wn >> 3) + 2 * j2 + nsel);
                uint32_t so = krow * 512 + ((cx ^ (krow & 31)) * 16);
                uint32_t r[4];
                ldsm4t(r, base + ATILEB_ + so);
                fb[2 * j2 + 0][0] = r[0]; fb[2 * j2 + 0][1] = r[1];
                fb[2 * j2 + 1][0] = r[2]; fb[2 * j2 + 1][1] = r[3];
            }
            #pragma unroll
            for (int i = 0; i < 4; i++)
                #pragma unroll
                for (int j = 0; j < 8; j++)
                    mma16816(acc[i][j], fa[i], fb[j]);
        }
        __syncthreads();
        if (++buf == 3) buf = 0;
    }

    const int g  = lane >> 2, tg = lane & 3;
    const size_t row0 = ar0 + wm, col0 = bc0 + wn;
    #pragma unroll
    for (int i = 0; i < 4; i++) {
        #pragma unroll
        for (int j = 0; j < 8; j++) {
            size_t col = col0 + j * 8 + tg * 2;
            float bx = 0.0f, by = 0.0f;
            if (BIAS) { bx = bias[col]; by = bias[col + 1]; }
            #pragma unroll
            for (int half = 0; half < 2; half++) {
                size_t row = row0 + i * 16 + g + half * 8;
                float vx = acc[i][j][2 * half + 0] + bx;
                float vy = acc[i][j][2 * half + 1] + by;
                size_t gi = row * (size_t)N + col;
                if (RES) { vx += res[gi]; vy += res[gi + 1]; }
                if (RELU) { vx = fmaxf(vx, 0.0f); vy = fmaxf(vy, 0.0f); }
                if (OHALF) {
                    Oh[gi >> 1] = __halves2half2(__float2half_rn(vx),
                                                 __float2half_rn(vy));
                } else {
                    float2 o; o.x = vx; o.y = vy;
                    *(float2*)(C + gi) = o;
                }
            }
        }
    }
}

// ------------------------- tensor-core attention -----------------------------
#define QT_    16
#define NTL_   128
#define SROW_  1032
#define SBY_   (QT_ * SROW_ * 4)
#define P_OFF_ SBY_
#define Q_OFF_ (P_OFF_ + QT_ * 2048)
#define KV_OFF_ (Q_OFF_ + 2048)
#define KVB_   16384
#define RINV_OFF_ (KV_OFF_ + 2 * KVB_)
#define ATT_SM_ (RINV_OFF_ + 64)

__global__ __launch_bounds__(256, 1) void attn_tc_k(
    const __half* __restrict__ qkvh, __half* __restrict__ oh)
{
    extern __shared__ char smc[];
    const uint32_t sb = smem_u32(smc);
    float* S    = (float*)smc;
    float* Rinv = (float*)(smc + RINV_OFF_);

    const int tid = threadIdx.x, wid = tid >> 5, lane = tid & 31;
    const int qt = (int)gridDim.x - 1 - (int)blockIdx.x;
    const int h = blockIdx.y, b = blockIdx.z;
    const int q0 = qt * QT_;
    const int nt = (q0 + QT_ + NTL_ - 1) / NTL_;

    const size_t hrow = (size_t)H_ * HS_;
    const __half* qg = qkvh + ((size_t)b * S_ + q0) * hrow + h * HS_;
    const __half* kg = qkvh + MD_     + (size_t)b * S_ * hrow + h * HS_;
    const __half* vg = qkvh + 2 * MD_ + (size_t)b * S_ * hrow + h * HS_;

    auto stageKV = [&](uint32_t dst, const __half* src, int t) {
        int j0 = t * NTL_;
        #pragma unroll
        for (int i = 0; i < 4; i++) {
            int id = tid + 256 * i;
            int r  = id >> 3;
            int cx = id & 7;
            uint32_t so = (uint32_t)(r * 128 + cx * 16);
            so ^= (so >> 3) & 0x70;
            CP16(dst + so, src + (size_t)(j0 + r) * hrow + cx * 8);
        }
    };

    if (tid < 128) {
        int r = tid >> 3, cx = tid & 7;
        uint32_t so = (uint32_t)(r * 128 + cx * 16);
        so ^= (so >> 3) & 0x70;
        CP16(sb + Q_OFF_ + so, qg + (size_t)r * hrow + cx * 8);
    }
    CPCOMMIT();
    stageKV(sb + KV_OFF_, kg, 0); CPCOMMIT();
    CPWAIT1();
    __syncthreads();

    uint32_t qf[4][4];
    {
        const int arow = lane & 15;
        const int akb  = (lane >> 4) * 16;
        #pragma unroll
        for (int ks = 0; ks < 4; ks++) {
            uint32_t so = (uint32_t)(arow * 128 + ks * 32 + akb);
            so ^= (so >> 3) & 0x70;
            ldsm4(qf[ks], sb + Q_OFF_ + so);
        }
    }

    for (int t = 0; t < nt; t++) {
        if (t + 1 < nt) { stageKV(sb + KV_OFF_ + ((t + 1) & 1) * KVB_, kg, t + 1); CPCOMMIT(); CPWAIT1(); }
        else            { CPWAIT0(); }
        __syncthreads();

        const uint32_t kb = sb + KV_OFF_ + (t & 1) * KVB_;
        #pragma unroll
        for (int sub = 0; sub < 2; sub++) {
            int n0 = (2 * wid + sub) * 8;
            float acc[4] = {0.0f, 0.0f, 0.0f, 0.0f};
            #pragma unroll
            for (int ks = 0; ks < 4; ks++) {
                uint32_t bf[2];
                uint32_t so = (uint32_t)((n0 + (lane & 7)) * 128 + ks * 32 + ((lane >> 3) & 1) * 16);
                so ^= (so >> 3) & 0x70;
                ldsm2(bf, kb + so);
                mma16816(acc, qf[ks], bf);
            }
            int g = lane >> 2, tg = lane & 3;
            int col = t * NTL_ + n0 + tg * 2;
            S[g * SROW_ + col]           = acc[0] * SCALE_;
            S[g * SROW_ + col + 1]       = acc[1] * SCALE_;
            S[(g + 8) * SROW_ + col]     = acc[2] * SCALE_;
            S[(g + 8) * SROW_ + col + 1] = acc[3] * SCALE_;
        }
        __syncthreads();
    }

    // V tile 0 prefetch overlaps the softmax below
    stageKV(sb + KV_OFF_, vg, 0); CPCOMMIT();

    {
        const int jmax = nt * NTL_;
        __half* P = (__half*)(smc + P_OFF_);
        #pragma unroll
        for (int qq = 0; qq < 2; qq++) {
            int r  = 2 * wid + qq;
            int nq = q0 + r + 1;
            float m = -1e30f;
            for (int j = lane; j < nq; j += 32) m = fmaxf(m, S[r * SROW_ + j]);
            #pragma unroll
            for (int st = 16; st > 0; st >>= 1)
                m = fmaxf(m, __shfl_xor_sync(0xffffffff, m, st));
            float sum = 0.0f;
            for (int j = lane; j < jmax; j += 32) {
                float e = 0.0f;
                if (j < nq) { e = __expf(S[r * SROW_ + j] - m); sum += e; }
                int ch = j >> 3;
                uint32_t off = (uint32_t)(r * 2048 + ((ch ^ (r & 7)) * 16) + (j & 7) * 2);
                *(__half*)((char*)P + off) = __float2half_rn(e);
            }
            #pragma unroll
            for (int st = 16; st > 0; st >>= 1)
                sum += __shfl_xor_sync(0xffffffff, sum, st);
            if (lane == 0) Rinv[r] = 1.0f / sum;
        }
    }
    __syncthreads();

    float oacc[4] = {0.0f, 0.0f, 0.0f, 0.0f};
    for (int t = 0; t < nt; t++) {
        if (t + 1 < nt) { stageKV(sb + KV_OFF_ + ((t + 1) & 1) * KVB_, vg, t + 1); CPCOMMIT(); CPWAIT1(); }
        else            { CPWAIT0(); }
        __syncthreads();

        const uint32_t vb = sb + KV_OFF_ + (t & 1) * KVB_;
        #pragma unroll
        for (int ks = 0; ks < 8; ks++) {
            uint32_t pf[4];
            {
                int r  = lane & 15;
                int ch = t * 16 + 2 * ks + (lane >> 4);
                uint32_t addr = (uint32_t)(P_OFF_ + r * 2048 + ((ch ^ (r & 7)) * 16));
                ldsm4(pf, sb + addr);
            }
            uint32_t vf[2];
            {
                int kr = ks * 16 + (lane & 15);
                int cx = wid;
                uint32_t so = (uint32_t)(kr * 128 + ((cx ^ (kr & 7)) * 16));
                ldsm2t(vf, vb + so);
            }
            mma16816(oacc, pf, vf);
        }
        __syncthreads();
    }

    {
        int g = lane >> 2, tg = lane & 3;
        int col = wid * 8 + tg * 2;
        #pragma unroll
        for (int half = 0; half < 2; half++) {
            int row = g + half * 8;
            float rv = Rinv[row];
            __half2 o = __halves2half2(__float2half_rn(oacc[2 * half + 0] * rv),
                                       __float2half_rn(oacc[2 * half + 1] * rv));
            *(__half2*)(oh + ((size_t)b * S_ + q0 + row) * hrow + h * HS_ + col) = o;
        }
    }
}

// ------------------------- driver -------------------------------------------
static cudaStream_t g_s2 = nullptr;
static cudaEvent_t  g_evFork = nullptr, g_evJ0 = nullptr, g_evJ1 = nullptr;

static inline void wsplit_on(cudaStream_t st, const float* src, __half* dst, size_t nfloat)
{
    int n4 = (int)(nfloat / 4);
    int quarter = (n4 >> 1) >> 2;
    wsplit_k<<<(quarter + 255) / 256, 256, 0, st>>>(
        (const float4*)src, (uint4*)dst, n4);
}

extern "C" void kernel_launch(void* const* d_in, const int* in_sizes, int n_in,
                              void* d_out, int out_size)
{
    const int*   idx   = (const int*)  d_in[0];
    const float* tok   = (const float*)d_in[1];
    const float* pos   = (const float*)d_in[2];
    const float* ln1g  = (const float*)d_in[3];
    const float* ln1b  = (const float*)d_in[4];
    const float* ln2g  = (const float*)d_in[5];
    const float* ln2b  = (const float*)d_in[6];
    const float* wq    = (const float*)d_in[7];
    const float* wk    = (const float*)d_in[8];
    const float* wv    = (const float*)d_in[9];
    const float* wo    = (const float*)d_in[10];
    const float* bo    = (const float*)d_in[11];
    const float* w1    = (const float*)d_in[12];
    const float* b1    = (const float*)d_in[13];
    const float* w2    = (const float*)d_in[14];
    const float* b2    = (const float*)d_in[15];
    const float* lnfg  = (const float*)d_in[16];
    const float* lnfb  = (const float*)d_in[17];
    const float* whead = (const float*)d_in[18];
    const float* bhead = (const float*)d_in[19];
    float* out = (float*)d_out;

    float *x, *xn;
    __half *qkvh, *ah, *hh, *wh;
    cudaGetSymbolAddress((void**)&x,    g_x);
    cudaGetSymbolAddress((void**)&xn,   g_xn);
    cudaGetSymbolAddress((void**)&qkvh, g_qkvh);
    cudaGetSymbolAddress((void**)&ah,   g_ah);
    cudaGetSymbolAddress((void**)&hh,   g_hh);
    cudaGetSymbolAddress((void**)&wh,   g_wh);

    cudaFuncSetAttribute(mma_gemm_k<false,false,false,true>,  cudaFuncAttributeMaxDynamicSharedMemorySize, SMTOT_);
    cudaFuncSetAttribute(mma_gemm_k<true,true,false,false>,   cudaFuncAttributeMaxDynamicSharedMemorySize, SMTOT_);
    cudaFuncSetAttribute(mma_gemm_k<true,false,true,true>,    cudaFuncAttributeMaxDynamicSharedMemorySize, SMTOT_);
    cudaFuncSetAttribute(mma_gemm_k<true,false,false,false>,  cudaFuncAttributeMaxDynamicSharedMemorySize, SMTOT_);
    cudaFuncSetAttribute(attn_tc_k, cudaFuncAttributeMaxDynamicSharedMemorySize, ATT_SM_);

    if (!g_s2) {
        cudaStreamCreateWithFlags(&g_s2, cudaStreamNonBlocking);
        cudaEventCreateWithFlags(&g_evFork, cudaEventDisableTiming);
        cudaEventCreateWithFlags(&g_evJ0,   cudaEventDisableTiming);
        cudaEventCreateWithFlags(&g_evJ1,   cudaEventDisableTiming);
    }

    dim3 blk(256);

    // ---- fork ALL weight conversion onto the side stream ----
    cudaEventRecord(g_evFork, 0);
    cudaStreamWaitEvent(g_s2, g_evFork, 0);
    wsplit_on(g_s2, wq, wh + WQ_OFF_, DD_);
    wsplit_on(g_s2, wk, wh + WK_OFF_, DD_);
    wsplit_on(g_s2, wv, wh + WV_OFF_, DD_);
    wsplit_on(g_s2, wo, wh + WO_OFF_, DD_);
    wsplit_on(g_s2, w1, wh + W1_OFF_, 4 * DD_);
    wsplit_on(g_s2, w2, wh + W2_OFF_, 4 * DD_);
    cudaEventRecord(g_evJ0, g_s2);
    wsplit_on(g_s2, wq + DD_,     wh + WQ_OFF_ + DD_,     3 * DD_);
    wsplit_on(g_s2, wk + DD_,     wh + WK_OFF_ + DD_,     3 * DD_);
    wsplit_on(g_s2, wv + DD_,     wh + WV_OFF_ + DD_,     3 * DD_);
    wsplit_on(g_s2, wo + DD_,     wh + WO_OFF_ + DD_,     3 * DD_);
    wsplit_on(g_s2, w1 + 4 * DD_, wh + W1_OFF_ + 4 * DD_, 12 * DD_);
    wsplit_on(g_s2, w2 + 4 * DD_, wh + W2_OFF_ + 4 * DD_, 12 * DD_);
    wsplit_on(g_s2, whead,        wh + WH_OFF_,           (size_t)D_ * V_);
    cudaEventRecord(g_evJ1, g_s2);

    // ---- layer 0 front: fused embed + LN1 ----
    embed_ln_k<<<M_, blk>>>(idx, (const float4*)tok, (const float4*)pos,
                            (const float4*)ln1g, (const float4*)ln1b,
                            (float4*)xn, (uint2*)ah);

    for (int l = 0; l < L_; l++) {
        if (l == 0) cudaStreamWaitEvent(0, g_evJ0, 0);
        if (l == 1) cudaStreamWaitEvent(0, g_evJ1, 0);

        size_t oq = WQ_OFF_ + (size_t)l * DD_;
        size_t oo = WO_OFF_ + (size_t)l * DD_;
        size_t o1 = W1_OFF_ + (size_t)l * 4 * DD_;
        size_t o2 = W2_OFF_ + (size_t)l * 4 * DD_;

        if (l > 0)
            layernorm_k<true><<<M_, blk>>>((const float4*)x, (const float4*)(ln1g + l * D_),
                                           (const float4*)(ln1b + l * D_), (float4*)xn,
                                           (uint2*)ah);

        // fused QKV -> fp16 qkv slabs
        mma_gemm_k<false,false,false,true><<<dim3(M_/128, D_/256, 3), blk, SMTOT_>>>(
            M_, D_, D_, ah, wh + oq, nullptr, nullptr, nullptr,
            (__half2*)qkvh, 4 * DD_, 0, MD_ / 2);

        attn_tc_k<<<dim3(S_ / QT_, H_, B_), 256, ATT_SM_>>>(qkvh, ah);

        // x = xn + att @ wo + bo
        mma_gemm_k<true,true,false,false><<<dim3(M_/128, D_/256), blk, SMTOT_>>>(
            M_, D_, D_, ah, wh + oo, bo + l * D_, xn, x,
            nullptr, 0, 0, 0);

        layernorm_k<true><<<M_, blk>>>((const float4*)x, (const float4*)(ln2g + l * D_),
                                       (const float4*)(ln2b + l * D_), (float4*)xn,
                                       (uint2*)ah);

        // h = relu(xn @ w1 + b1)  -> fp16 directly
        mma_gemm_k<true,false,true,true><<<dim3(M_/128, DFF_/256), blk, SMTOT_>>>(
            M_, DFF_, D_, ah, wh + o1,
            b1 + (size_t)l * DFF_, nullptr, nullptr,
            (__half2*)hh, 0, 0, 0);

        // x = xn + h @ w2 + b2
        mma_gemm_k<true,true,false,false><<<dim3(M_/128, D_/256), blk, SMTOT_>>>(
            M_, D_, DFF_, hh, wh + o2,
            b2 + l * D_, xn, x, nullptr, 0, 0, 0);
    }

    // final LN: fp16 output only (fp32 xn is dead here)
    layernorm_k<false><<<M_, blk>>>((const float4*)x, (const float4*)lnfg,
                                    (const float4*)lnfb, nullptr,
                                    (uint2*)ah);

    // logits = xn @ w_head + b_head
    mma_gemm_k<true,false,false,false><<<dim3(M_/128, V_/256), blk, SMTOT_>>>(
        M_, V_, D_, ah, wh + WH_OFF_,
        bhead, nullptr, out, nullptr, 0, 0, 0);
}

// round 17
// speedup vs baseline: 1.2213x; 1.0438x over previous
#include <cuda_runtime.h>
#include <cuda_fp16.h>
#include <cstdint>
#include <math.h>

// ---------------------------------------------------------------------------
// MinGPT forward.  B=4, S=1024, D=1024, H=16, HS=64, L=4, DFF=4096, V=32000.
// Round 17: 4-stage smem ring in the GEMM -> one __syncthreads per K-chunk.
// Everything else identical to R16 (best: 2921 us, rel_err 5.156e-4).
// ---------------------------------------------------------------------------

#define B_  4
#define S_  1024
#define D_  1024
#define H_  16
#define HS_ 64
#define L_  4
#define DFF_ 4096
#define V_  32000
#define M_  (B_ * S_)
#define MD_ ((size_t)M_ * D_)
#define EPS_ 1e-5f
#define SCALE_ 0.03125f        // D^-0.5 = 1/32 (reference uses d_model)

// ------------------------- scratch -----------------------------------------
__device__ float g_x  [M_ * D_];
__device__ float g_xn [M_ * D_];

__device__ __align__(16) __half g_qkvh[3 * M_ * D_];
__device__ __align__(16) __half g_ah[M_ * D_];
__device__ __align__(16) __half g_hh[M_ * DFF_];

#define DD_      ((size_t)D_ * D_)
#define WQ_OFF_  ((size_t)0)
#define WK_OFF_  (4 * DD_)
#define WV_OFF_  (8 * DD_)
#define WO_OFF_  (12 * DD_)
#define W1_OFF_  (16 * DD_)
#define W2_OFF_  (32 * DD_)
#define WH_OFF_  (48 * DD_)
#define WT_TOT_  (48 * DD_ + (size_t)D_ * V_)
__device__ __align__(16) __half g_wh[WT_TOT_];

// ------------------------- PTX helpers --------------------------------------
__device__ __forceinline__ uint32_t smem_u32(const void* p) {
    uint32_t a;
    asm("{ .reg .u64 t; cvta.to.shared.u64 t, %1; cvt.u32.u64 %0, t; }"
        : "=r"(a) : "l"(p));
    return a;
}
#define CP16(dst, src) \
    asm volatile("cp.async.cg.shared.global [%0], [%1], 16;" :: "r"(dst), "l"(src))
#define CPCOMMIT() asm volatile("cp.async.commit_group;" ::: "memory")
#define CPWAIT0()  asm volatile("cp.async.wait_group 0;" ::: "memory")
#define CPWAIT1()  asm volatile("cp.async.wait_group 1;" ::: "memory")
#define CPWAIT2()  asm volatile("cp.async.wait_group 2;" ::: "memory")

__device__ __forceinline__ void ldsm4(uint32_t* r, uint32_t addr) {
    asm volatile("ldmatrix.sync.aligned.m8n8.x4.shared.b16 {%0,%1,%2,%3}, [%4];"
        : "=r"(r[0]), "=r"(r[1]), "=r"(r[2]), "=r"(r[3]) : "r"(addr));
}
__device__ __forceinline__ void ldsm4t(uint32_t* r, uint32_t addr) {
    asm volatile("ldmatrix.sync.aligned.m8n8.x4.trans.shared.b16 {%0,%1,%2,%3}, [%4];"
        : "=r"(r[0]), "=r"(r[1]), "=r"(r[2]), "=r"(r[3]) : "r"(addr));
}
__device__ __forceinline__ void ldsm2(uint32_t* r, uint32_t addr) {
    asm volatile("ldmatrix.sync.aligned.m8n8.x2.shared.b16 {%0,%1}, [%2];"
        : "=r"(r[0]), "=r"(r[1]) : "r"(addr));
}
__device__ __forceinline__ void ldsm2t(uint32_t* r, uint32_t addr) {
    asm volatile("ldmatrix.sync.aligned.m8n8.x2.trans.shared.b16 {%0,%1}, [%2];"
        : "=r"(r[0]), "=r"(r[1]) : "r"(addr));
}
__device__ __forceinline__ void mma16816(float* d, const uint32_t* a, const uint32_t* b) {
    asm volatile(
        "mma.sync.aligned.m16n8k16.row.col.f32.f16.f16.f32 "
        "{%0,%1,%2,%3}, {%4,%5,%6,%7}, {%8,%9}, {%0,%1,%2,%3};"
        : "+f"(d[0]), "+f"(d[1]), "+f"(d[2]), "+f"(d[3])
        : "r"(a[0]), "r"(a[1]), "r"(a[2]), "r"(a[3]), "r"(b[0]), "r"(b[1]));
}

__device__ __forceinline__ uint32_t pack2h(float a, float b) {
    __half2 h = __halves2half2(__float2half_rn(a), __float2half_rn(b));
    return *(uint32_t*)&h;
}

// block reduction over 256 threads via warp shuffles
__device__ __forceinline__ float blk_sum(float v, float* ws, int tid) {
    #pragma unroll
    for (int st = 16; st > 0; st >>= 1)
        v += __shfl_xor_sync(0xffffffff, v, st);
    if ((tid & 31) == 0) ws[tid >> 5] = v;
    __syncthreads();
    if (tid < 32) {
        float w = (tid < 8) ? ws[tid] : 0.0f;
        #pragma unroll
        for (int st = 4; st > 0; st >>= 1)
            w += __shfl_xor_sync(0xffffffff, w, st);
        if (tid == 0) ws[0] = w;
    }
    __syncthreads();
    return ws[0];
}

// ------------------------- LN core ------------------------------------------
template<bool WRITEY>
__device__ __forceinline__ void ln_finish(
    float4 xv, int tid, size_t i,
    const float4* __restrict__ g, const float4* __restrict__ bb,
    float4* __restrict__ y, uint2* __restrict__ oh,
    float* ws1, float* ws2)
{
    float s = xv.x + xv.y + xv.z + xv.w;
    float mu = blk_sum(s, ws1, tid) * (1.0f / D_);

    float dx = xv.x - mu, dy = xv.y - mu, dz = xv.z - mu, dw = xv.w - mu;
    float s2 = dx * dx + dy * dy + dz * dz + dw * dw;
    float var = blk_sum(s2, ws2, tid) * (1.0f / D_);
    float inv = rsqrtf(var + EPS_);

    float4 gv = g[tid], bv = bb[tid];
    float4 o;
    o.x = dx * inv * gv.x + bv.x;
    o.y = dy * inv * gv.y + bv.y;
    o.z = dz * inv * gv.z + bv.z;
    o.w = dw * inv * gv.w + bv.w;
    if (WRITEY) y[i] = o;

    uint2 hp;
    hp.x = pack2h(o.x, o.y);
    hp.y = pack2h(o.z, o.w);
    oh[i] = hp;
}

template<bool WRITEY>
__global__ __launch_bounds__(256) void layernorm_k(
    const float4* __restrict__ x, const float4* __restrict__ g,
    const float4* __restrict__ bb, float4* __restrict__ y,
    uint2* __restrict__ oh)
{
    __shared__ float ws1[8], ws2[8];
    int row = blockIdx.x, tid = threadIdx.x;
    size_t i = (size_t)row * 256 + tid;
    float4 xv = x[i];
    ln_finish<WRITEY>(xv, tid, i, g, bb, y, oh, ws1, ws2);
}

__global__ __launch_bounds__(256) void embed_ln_k(
    const int* __restrict__ idx, const float4* __restrict__ tok,
    const float4* __restrict__ pos,
    const float4* __restrict__ g, const float4* __restrict__ bb,
    float4* __restrict__ y, uint2* __restrict__ oh)
{
    __shared__ float ws1[8], ws2[8];
    int row = blockIdx.x, tid = threadIdx.x;
    int s   = row & (S_ - 1);
    int t   = idx[row];
    float4 tv = tok[(size_t)t * 256 + tid];
    float4 pv = pos[(size_t)s * 256 + tid];
    float4 xv;
    xv.x = tv.x + pv.x; xv.y = tv.y + pv.y;
    xv.z = tv.z + pv.z; xv.w = tv.w + pv.w;
    size_t i = (size_t)row * 256 + tid;
    ln_finish<true>(xv, tid, i, g, bb, y, oh, ws1, ws2);
}

// ------------------------- fp32 -> fp16 (weights) ----------------------------
__global__ __launch_bounds__(256) void wsplit_k(
    const float4* __restrict__ x, uint4* __restrict__ h, int n4)
{
    int npair = n4 >> 1;
    int quarter = npair >> 2;
    int i = blockIdx.x * 256 + threadIdx.x;
    if (i >= quarter) return;
    #pragma unroll
    for (int m = 0; m < 4; m++) {
        int p = i + m * quarter;
        float4 v0 = x[2 * p];
        float4 v1 = x[2 * p + 1];
        uint4 o;
        o.x = pack2h(v0.x, v0.y);
        o.y = pack2h(v0.z, v0.w);
        o.z = pack2h(v1.x, v1.y);
        o.w = pack2h(v1.z, v1.w);
        h[p] = o;
    }
}

// ------------------------- mma.sync GEMM (4-stage ring, 1 sync/chunk) --------
#define ATILEB_ 16384
#define BTILEB_ 32768
#define BUFB_   (ATILEB_ + BTILEB_)        // 48 KB
#define SMTOT_  (4 * BUFB_)                // 192 KB

template<bool BIAS, bool RES, bool RELU, bool OHALF>
__global__ __launch_bounds__(256, 1) void mma_gemm_k(
    int M, int N, int K,
    const __half* __restrict__ Ah,
    const __half* __restrict__ Bw,
    const float* __restrict__ bias, const float* __restrict__ res,
    float* __restrict__ C,
    __half2* __restrict__ Oh,
    size_t bzS, size_t czS, size_t ozS)
{
    extern __shared__ char smem[];
    const uint32_t sb = smem_u32(smem);
    const int tid = threadIdx.x, wid = tid >> 5, lane = tid & 31;
    const int mb = blockIdx.x, nb = blockIdx.y;
    Bw += blockIdx.z * bzS;
    C  += blockIdx.z * czS;
    if (OHALF) Oh += blockIdx.z * ozS;
    const size_t ar0 = (size_t)mb * 128, bc0 = (size_t)nb * 256;
    const int wm = (wid >> 2) * 64, wn = (wid & 3) * 64;

    float acc[4][8][4];
    #pragma unroll
    for (int i = 0; i < 4; i++)
        #pragma unroll
        for (int j = 0; j < 8; j++)
            #pragma unroll
            for (int e = 0; e < 4; e++) acc[i][j][e] = 0.0f;

    const int nch = K >> 6;

    auto fill = [&](int buf, int c) {
        const size_t kof = (size_t)c << 6;
        const uint32_t bb = sb + buf * BUFB_;
        #pragma unroll
        for (int i = 0; i < 4; i++) {
            int id = tid + 256 * i;
            int r  = id >> 3;
            int cx = id & 7;
            uint32_t so = (uint32_t)(r * 128 + cx * 16);
            so ^= (so >> 3) & 0x70;
            size_t ai = (ar0 + r) * (size_t)K + kof + cx * 8;
            CP16(bb + so, Ah + ai);
        }
        #pragma unroll
        for (int i = 0; i < 8; i++) {
            int id = tid + 256 * i;
            int kr = id >> 5;
            int cx = id & 31;
            uint32_t so = (uint32_t)(kr * 512 + ((cx ^ (kr & 31)) * 16));
            size_t bi = (kof + kr) * (size_t)N + bc0 + cx * 8;
            CP16(bb + ATILEB_ + so, Bw + bi);
        }
    };

    fill(0, 0); CPCOMMIT();
    fill(1, 1); CPCOMMIT();

    uint32_t fa[4][4], fb[8][2];
    const int arow = wm + (lane & 15);
    const int akb  = (lane >> 4) * 16;
    const int krl  = lane & 15;
    const int nsel = lane >> 4;

    for (int c = 0; c < nch; c++) {
        // prefetch chunk c+2 into ring slot (c+2)&3; slot (c+3)&3 is the only
        // buffer a 1-chunk-ahead warp could write, disjoint from slot c&3 being
        // read -> the end-of-chunk barrier is unnecessary with 4 buffers.
        if (c + 2 < nch) {
            fill((c + 2) & 3, c + 2); CPCOMMIT(); CPWAIT2();
        } else if (c + 1 < nch) { CPWAIT1(); }
        else                    { CPWAIT0(); }
        __syncthreads();

        const uint32_t base = sb + (c & 3) * BUFB_;
        #pragma unroll
        for (int ks = 0; ks < 4; ks++) {
            #pragma unroll
            for (int i = 0; i < 4; i++) {
                uint32_t so = (uint32_t)((arow + i * 16) * 128 + ks * 32 + akb);
                so ^= (so >> 3) & 0x70;
                ldsm4(fa[i], base + so);
            }
            const uint32_t krow = (uint32_t)(ks * 16 + krl);
            #pragma unroll
            for (int j2 = 0; j2 < 4; j2++) {
                uint32_t cx = (uint32_t)((wn >> 3) + 2 * j2 + nsel);
                uint32_t so = krow * 512 + ((cx ^ (krow & 31)) * 16);
                uint32_t r[4];
                ldsm4t(r, base + ATILEB_ + so);
                fb[2 * j2 + 0][0] = r[0]; fb[2 * j2 + 0][1] = r[1];
                fb[2 * j2 + 1][0] = r[2]; fb[2 * j2 + 1][1] = r[3];
            }
            #pragma unroll
            for (int i = 0; i < 4; i++)
                #pragma unroll
                for (int j = 0; j < 8; j++)
                    mma16816(acc[i][j], fa[i], fb[j]);
        }
        // no end-of-chunk __syncthreads (4-stage ring makes it safe)
    }

    const int g  = lane >> 2, tg = lane & 3;
    const size_t row0 = ar0 + wm, col0 = bc0 + wn;
    #pragma unroll
    for (int i = 0; i < 4; i++) {
        #pragma unroll
        for (int j = 0; j < 8; j++) {
            size_t col = col0 + j * 8 + tg * 2;
            float bx = 0.0f, by = 0.0f;
            if (BIAS) { bx = bias[col]; by = bias[col + 1]; }
            #pragma unroll
            for (int half = 0; half < 2; half++) {
                size_t row = row0 + i * 16 + g + half * 8;
                float vx = acc[i][j][2 * half + 0] + bx;
                float vy = acc[i][j][2 * half + 1] + by;
                size_t gi = row * (size_t)N + col;
                if (RES) { vx += res[gi]; vy += res[gi + 1]; }
                if (RELU) { vx = fmaxf(vx, 0.0f); vy = fmaxf(vy, 0.0f); }
                if (OHALF) {
                    Oh[gi >> 1] = __halves2half2(__float2half_rn(vx),
                                                 __float2half_rn(vy));
                } else {
                    float2 o; o.x = vx; o.y = vy;
                    *(float2*)(C + gi) = o;
                }
            }
        }
    }
}

// ------------------------- tensor-core attention -----------------------------
#define QT_    16
#define NTL_   128
#define SROW_  1032
#define SBY_   (QT_ * SROW_ * 4)
#define P_OFF_ SBY_
#define Q_OFF_ (P_OFF_ + QT_ * 2048)
#define KV_OFF_ (Q_OFF_ + 2048)
#define KVB_   16384
#define RINV_OFF_ (KV_OFF_ + 2 * KVB_)
#define ATT_SM_ (RINV_OFF_ + 64)

__global__ __launch_bounds__(256, 1) void attn_tc_k(
    const __half* __restrict__ qkvh, __half* __restrict__ oh)
{
    extern __shared__ char smc[];
    const uint32_t sb = smem_u32(smc);
    float* S    = (float*)smc;
    float* Rinv = (float*)(smc + RINV_OFF_);

    const int tid = threadIdx.x, wid = tid >> 5, lane = tid & 31;
    const int qt = (int)gridDim.x - 1 - (int)blockIdx.x;
    const int h = blockIdx.y, b = blockIdx.z;
    const int q0 = qt * QT_;
    const int nt = (q0 + QT_ + NTL_ - 1) / NTL_;

    const size_t hrow = (size_t)H_ * HS_;
    const __half* qg = qkvh + ((size_t)b * S_ + q0) * hrow + h * HS_;
    const __half* kg = qkvh + MD_     + (size_t)b * S_ * hrow + h * HS_;
    const __half* vg = qkvh + 2 * MD_ + (size_t)b * S_ * hrow + h * HS_;

    auto stageKV = [&](uint32_t dst, const __half* src, int t) {
        int j0 = t * NTL_;
        #pragma unroll
        for (int i = 0; i < 4; i++) {
            int id = tid + 256 * i;
            int r  = id >> 3;
            int cx = id & 7;
            uint32_t so = (uint32_t)(r * 128 + cx * 16);
            so ^= (so >> 3) & 0x70;
            CP16(dst + so, src + (size_t)(j0 + r) * hrow + cx * 8);
        }
    };

    if (tid < 128) {
        int r = tid >> 3, cx = tid & 7;
        uint32_t so = (uint32_t)(r * 128 + cx * 16);
        so ^= (so >> 3) & 0x70;
        CP16(sb + Q_OFF_ + so, qg + (size_t)r * hrow + cx * 8);
    }
    CPCOMMIT();
    stageKV(sb + KV_OFF_, kg, 0); CPCOMMIT();
    CPWAIT1();
    __syncthreads();

    uint32_t qf[4][4];
    {
        const int arow = lane & 15;
        const int akb  = (lane >> 4) * 16;
        #pragma unroll
        for (int ks = 0; ks < 4; ks++) {
            uint32_t so = (uint32_t)(arow * 128 + ks * 32 + akb);
            so ^= (so >> 3) & 0x70;
            ldsm4(qf[ks], sb + Q_OFF_ + so);
        }
    }

    for (int t = 0; t < nt; t++) {
        if (t + 1 < nt) { stageKV(sb + KV_OFF_ + ((t + 1) & 1) * KVB_, kg, t + 1); CPCOMMIT(); CPWAIT1(); }
        else            { CPWAIT0(); }
        __syncthreads();

        const uint32_t kb = sb + KV_OFF_ + (t & 1) * KVB_;
        #pragma unroll
        for (int sub = 0; sub < 2; sub++) {
            int n0 = (2 * wid + sub) * 8;
            float acc[4] = {0.0f, 0.0f, 0.0f, 0.0f};
            #pragma unroll
            for (int ks = 0; ks < 4; ks++) {
                uint32_t bf[2];
                uint32_t so = (uint32_t)((n0 + (lane & 7)) * 128 + ks * 32 + ((lane >> 3) & 1) * 16);
                so ^= (so >> 3) & 0x70;
                ldsm2(bf, kb + so);
                mma16816(acc, qf[ks], bf);
            }
            int g = lane >> 2, tg = lane & 3;
            int col = t * NTL_ + n0 + tg * 2;
            S[g * SROW_ + col]           = acc[0] * SCALE_;
            S[g * SROW_ + col + 1]       = acc[1] * SCALE_;
            S[(g + 8) * SROW_ + col]     = acc[2] * SCALE_;
            S[(g + 8) * SROW_ + col + 1] = acc[3] * SCALE_;
        }
        __syncthreads();
    }

    // V tile 0 prefetch overlaps the softmax below
    stageKV(sb + KV_OFF_, vg, 0); CPCOMMIT();

    {
        const int jmax = nt * NTL_;
        __half* P = (__half*)(smc + P_OFF_);
        #pragma unroll
        for (int qq = 0; qq < 2; qq++) {
            int r  = 2 * wid + qq;
            int nq = q0 + r + 1;
            float m = -1e30f;
            for (int j = lane; j < nq; j += 32) m = fmaxf(m, S[r * SROW_ + j]);
            #pragma unroll
            for (int st = 16; st > 0; st >>= 1)
                m = fmaxf(m, __shfl_xor_sync(0xffffffff, m, st));
            float sum = 0.0f;
            for (int j = lane; j < jmax; j += 32) {
                float e = 0.0f;
                if (j < nq) { e = __expf(S[r * SROW_ + j] - m); sum += e; }
                int ch = j >> 3;
                uint32_t off = (uint32_t)(r * 2048 + ((ch ^ (r & 7)) * 16) + (j & 7) * 2);
                *(__half*)((char*)P + off) = __float2half_rn(e);
            }
            #pragma unroll
            for (int st = 16; st > 0; st >>= 1)
                sum += __shfl_xor_sync(0xffffffff, sum, st);
            if (lane == 0) Rinv[r] = 1.0f / sum;
        }
    }
    __syncthreads();

    float oacc[4] = {0.0f, 0.0f, 0.0f, 0.0f};
    for (int t = 0; t < nt; t++) {
        if (t + 1 < nt) { stageKV(sb + KV_OFF_ + ((t + 1) & 1) * KVB_, vg, t + 1); CPCOMMIT(); CPWAIT1(); }
        else            { CPWAIT0(); }
        __syncthreads();

        const uint32_t vb = sb + KV_OFF_ + (t & 1) * KVB_;
        #pragma unroll
        for (int ks = 0; ks < 8; ks++) {
            uint32_t pf[4];
            {
                int r  = lane & 15;
                int ch = t * 16 + 2 * ks + (lane >> 4);
                uint32_t addr = (uint32_t)(P_OFF_ + r * 2048 + ((ch ^ (r & 7)) * 16));
                ldsm4(pf, sb + addr);
            }
            uint32_t vf[2];
            {
                int kr = ks * 16 + (lane & 15);
                int cx = wid;
                uint32_t so = (uint32_t)(kr * 128 + ((cx ^ (kr & 7)) * 16));
                ldsm2t(vf, vb + so);
            }
            mma16816(oacc, pf, vf);
        }
        __syncthreads();
    }

    {
        int g = lane >> 2, tg = lane & 3;
        int col = wid * 8 + tg * 2;
        #pragma unroll
        for (int half = 0; half < 2; half++) {
            int row = g + half * 8;
            float rv = Rinv[row];
            __half2 o = __halves2half2(__float2half_rn(oacc[2 * half + 0] * rv),
                                       __float2half_rn(oacc[2 * half + 1] * rv));
            *(__half2*)(oh + ((size_t)b * S_ + q0 + row) * hrow + h * HS_ + col) = o;
        }
    }
}

// ------------------------- driver -------------------------------------------
static cudaStream_t g_s2 = nullptr;
static cudaEvent_t  g_evFork = nullptr, g_evJ0 = nullptr, g_evJ1 = nullptr;

static inline void wsplit_on(cudaStream_t st, const float* src, __half* dst, size_t nfloat)
{
    int n4 = (int)(nfloat / 4);
    int quarter = (n4 >> 1) >> 2;
    wsplit_k<<<(quarter + 255) / 256, 256, 0, st>>>(
        (const float4*)src, (uint4*)dst, n4);
}

extern "C" void kernel_launch(void* const* d_in, const int* in_sizes, int n_in,
                              void* d_out, int out_size)
{
    const int*   idx   = (const int*)  d_in[0];
    const float* tok   = (const float*)d_in[1];
    const float* pos   = (const float*)d_in[2];
    const float* ln1g  = (const float*)d_in[3];
    const float* ln1b  = (const float*)d_in[4];
    const float* ln2g  = (const float*)d_in[5];
    const float* ln2b  = (const float*)d_in[6];
    const float* wq    = (const float*)d_in[7];
    const float* wk    = (const float*)d_in[8];
    const float* wv    = (const float*)d_in[9];
    const float* wo    = (const float*)d_in[10];
    const float* bo    = (const float*)d_in[11];
    const float* w1    = (const float*)d_in[12];
    const float* b1    = (const float*)d_in[13];
    const float* w2    = (const float*)d_in[14];
    const float* b2    = (const float*)d_in[15];
    const float* lnfg  = (const float*)d_in[16];
    const float* lnfb  = (const float*)d_in[17];
    const float* whead = (const float*)d_in[18];
    const float* bhead = (const float*)d_in[19];
    float* out = (float*)d_out;

    float *x, *xn;
    __half *qkvh, *ah, *hh, *wh;
    cudaGetSymbolAddress((void**)&x,    g_x);
    cudaGetSymbolAddress((void**)&xn,   g_xn);
    cudaGetSymbolAddress((void**)&qkvh, g_qkvh);
    cudaGetSymbolAddress((void**)&ah,   g_ah);
    cudaGetSymbolAddress((void**)&hh,   g_hh);
    cudaGetSymbolAddress((void**)&wh,   g_wh);

    cudaFuncSetAttribute(mma_gemm_k<false,false,false,true>,  cudaFuncAttributeMaxDynamicSharedMemorySize, SMTOT_);
    cudaFuncSetAttribute(mma_gemm_k<true,true,false,false>,   cudaFuncAttributeMaxDynamicSharedMemorySize, SMTOT_);
    cudaFuncSetAttribute(mma_gemm_k<true,false,true,true>,    cudaFuncAttributeMaxDynamicSharedMemorySize, SMTOT_);
    cudaFuncSetAttribute(mma_gemm_k<true,false,false,false>,  cudaFuncAttributeMaxDynamicSharedMemorySize, SMTOT_);
    cudaFuncSetAttribute(attn_tc_k, cudaFuncAttributeMaxDynamicSharedMemorySize, ATT_SM_);

    if (!g_s2) {
        cudaStreamCreateWithFlags(&g_s2, cudaStreamNonBlocking);
        cudaEventCreateWithFlags(&g_evFork, cudaEventDisableTiming);
        cudaEventCreateWithFlags(&g_evJ0,   cudaEventDisableTiming);
        cudaEventCreateWithFlags(&g_evJ1,   cudaEventDisableTiming);
    }

    dim3 blk(256);

    // ---- fork ALL weight conversion onto the side stream ----
    cudaEventRecord(g_evFork, 0);
    cudaStreamWaitEvent(g_s2, g_evFork, 0);
    wsplit_on(g_s2, wq, wh + WQ_OFF_, DD_);
    wsplit_on(g_s2, wk, wh + WK_OFF_, DD_);
    wsplit_on(g_s2, wv, wh + WV_OFF_, DD_);
    wsplit_on(g_s2, wo, wh + WO_OFF_, DD_);
    wsplit_on(g_s2, w1, wh + W1_OFF_, 4 * DD_);
    wsplit_on(g_s2, w2, wh + W2_OFF_, 4 * DD_);
    cudaEventRecord(g_evJ0, g_s2);
    wsplit_on(g_s2, wq + DD_,     wh + WQ_OFF_ + DD_,     3 * DD_);
    wsplit_on(g_s2, wk + DD_,     wh + WK_OFF_ + DD_,     3 * DD_);
    wsplit_on(g_s2, wv + DD_,     wh + WV_OFF_ + DD_,     3 * DD_);
    wsplit_on(g_s2, wo + DD_,     wh + WO_OFF_ + DD_,     3 * DD_);
    wsplit_on(g_s2, w1 + 4 * DD_, wh + W1_OFF_ + 4 * DD_, 12 * DD_);
    wsplit_on(g_s2, w2 + 4 * DD_, wh + W2_OFF_ + 4 * DD_, 12 * DD_);
    wsplit_on(g_s2, whead,        wh + WH_OFF_,           (size_t)D_ * V_);
    cudaEventRecord(g_evJ1, g_s2);

    // ---- layer 0 front: fused embed + LN1 ----
    embed_ln_k<<<M_, blk>>>(idx, (const float4*)tok, (const float4*)pos,
                            (const float4*)ln1g, (const float4*)ln1b,
                            (float4*)xn, (uint2*)ah);

    for (int l = 0; l < L_; l++) {
        if (l == 0) cudaStreamWaitEvent(0, g_evJ0, 0);
        if (l == 1) cudaStreamWaitEvent(0, g_evJ1, 0);

        size_t oq = WQ_OFF_ + (size_t)l * DD_;
        size_t oo = WO_OFF_ + (size_t)l * DD_;
        size_t o1 = W1_OFF_ + (size_t)l * 4 * DD_;
        size_t o2 = W2_OFF_ + (size_t)l * 4 * DD_;

        if (l > 0)
            layernorm_k<true><<<M_, blk>>>((const float4*)x, (const float4*)(ln1g + l * D_),
                                           (const float4*)(ln1b + l * D_), (float4*)xn,
                                           (uint2*)ah);

        // fused QKV -> fp16 qkv slabs
        mma_gemm_k<false,false,false,true><<<dim3(M_/128, D_/256, 3), blk, SMTOT_>>>(
            M_, D_, D_, ah, wh + oq, nullptr, nullptr, nullptr,
            (__half2*)qkvh, 4 * DD_, 0, MD_ / 2);

        attn_tc_k<<<dim3(S_ / QT_, H_, B_), 256, ATT_SM_>>>(qkvh, ah);

        // x = xn + att @ wo + bo
        mma_gemm_k<true,true,false,false><<<dim3(M_/128, D_/256), blk, SMTOT_>>>(
            M_, D_, D_, ah, wh + oo, bo + l * D_, xn, x,
            nullptr, 0, 0, 0);

        layernorm_k<true><<<M_, blk>>>((const float4*)x, (const float4*)(ln2g + l * D_),
                                       (const float4*)(ln2b + l * D_), (float4*)xn,
                                       (uint2*)ah);

        // h = relu(xn @ w1 + b1)  -> fp16 directly
        mma_gemm_k<true,false,true,true><<<dim3(M_/128, DFF_/256), blk, SMTOT_>>>(
            M_, DFF_, D_, ah, wh + o1,
            b1 + (size_t)l * DFF_, nullptr, nullptr,
            (__half2*)hh, 0, 0, 0);

        // x = xn + h @ w2 + b2
        mma_gemm_k<true,true,false,false><<<dim3(M_/128, D_/256), blk, SMTOT_>>>(
            M_, D_, DFF_, hh, wh + o2,
            b2 + l * D_, xn, x, nullptr, 0, 0, 0);
    }

    // final LN: fp16 output only (fp32 xn is dead here)
    layernorm_k<false><<<M_, blk>>>((const float4*)x, (const float4*)lnfg,
                                    (const float4*)lnfb, nullptr,
                                    (uint2*)ah);

    // logits = xn @ w_head + b_head
    mma_gemm_k<true,false,false,false><<<dim3(M_/128, V_/256), blk, SMTOT_>>>(
        M_, V_, D_, ah, wh + WH_OFF_,
        bhead, nullptr, out, nullptr, 0, 0, 0);
}